// round 6
// baseline (speedup 1.0000x reference)
#include <cuda_runtime.h>
#include <math.h>
#include <stdint.h>

// Problem constants
#define BB 4
#define SS 2048
#define DD 1024
#define HH 16
#define HD 64
#define LOG2E 1.4426950408889634f

// Scratch (__device__ globals per allocation rules)
__device__ float g_qkv[(size_t)BB * SS * 3 * DD];   // [B,S,3D] (tf32-rounded)
__device__ float g_y[(size_t)BB * SS * DD];         // [B,S,D]  (tf32-rounded)
__device__ float g_xc[(size_t)BB * SS * DD];        // x, tf32-rounded
__device__ float g_wta[(size_t)3 * DD * DD];        // W_attn^T [3D][D], rounded
__device__ float g_wtp[(size_t)DD * DD];            // W_proj^T [D][D], rounded

__device__ __forceinline__ uint32_t cvt_tf32(float f) {
    uint32_t r;
    asm("cvt.rna.tf32.f32 %0, %1;" : "=r"(r) : "f"(f));
    return r;
}
__device__ __forceinline__ uint32_t smem_u32(const void* p) {
    uint32_t a;
    asm("{ .reg .u64 t; cvta.to.shared.u64 t, %1; cvt.u32.u64 %0, t; }" : "=r"(a) : "l"(p));
    return a;
}

#define MMA_TF32(acc, a0, a1, a2, a3, b0, b1) \
    asm volatile( \
        "mma.sync.aligned.m16n8k8.row.col.f32.tf32.tf32.f32 " \
        "{%0,%1,%2,%3}, {%4,%5,%6,%7}, {%8,%9}, {%0,%1,%2,%3};" \
        : "+f"((acc)[0]), "+f"((acc)[1]), "+f"((acc)[2]), "+f"((acc)[3]) \
        : "r"(a0), "r"(a1), "r"(a2), "r"(a3), "r"(b0), "r"(b1))

#define LDMX4(r0, r1, r2, r3, addr) \
    asm volatile("ldmatrix.sync.aligned.m8n8.x4.shared.b16 {%0,%1,%2,%3}, [%4];" \
        : "=r"(r0), "=r"(r1), "=r"(r2), "=r"(r3) : "r"(addr))

#define CP16(dst, src) \
    asm volatile("cp.async.cg.shared.global [%0], [%1], 16;" :: "r"(dst), "l"(src))
#define CP_COMMIT() asm volatile("cp.async.commit_group;" ::: "memory")
#define CP_WAIT(n)  asm volatile("cp.async.wait_group %0;" :: "n"(n) : "memory")

// ---------------------------------------------------------------------------
// Prep kernels
// ---------------------------------------------------------------------------
__global__ void cvt_round4(const float4* __restrict__ in, float4* __restrict__ out, int n4)
{
    int i = blockIdx.x * blockDim.x + threadIdx.x;
    if (i < n4) {
        float4 v = in[i];
        v.x = __uint_as_float(cvt_tf32(v.x));
        v.y = __uint_as_float(cvt_tf32(v.y));
        v.z = __uint_as_float(cvt_tf32(v.z));
        v.w = __uint_as_float(cvt_tf32(v.w));
        out[i] = v;
    }
}

// in[K][N] row-major -> out[N][K] row-major, tf32-rounded
__global__ void transpose_cvt(const float* __restrict__ in, float* __restrict__ out,
                              int K, int N)
{
    __shared__ float t[32][33];
    const int n0 = blockIdx.x * 32;
    const int k0 = blockIdx.y * 32;
#pragma unroll
    for (int i = 0; i < 32; i += 8)
        t[threadIdx.y + i][threadIdx.x] =
            in[(size_t)(k0 + threadIdx.y + i) * N + n0 + threadIdx.x];
    __syncthreads();
#pragma unroll
    for (int i = 0; i < 32; i += 8)
        out[(size_t)(n0 + threadIdx.y + i) * K + k0 + threadIdx.x] =
            __uint_as_float(cvt_tf32(t[threadIdx.x][threadIdx.y + i]));
}

// ---------------------------------------------------------------------------
// TF32 GEMM (validated round 5 — at legacy-HMMA roofline, unchanged)
// C[M, Ntot] = A[M,1024] @ Wt[Ntot,1024]^T + bias
// ---------------------------------------------------------------------------
#define GK 1024
#define KT 16
#define NKT (GK / KT)
#define GST 20
#define G_ASTAGE (128 * GST)
#define G_BSTAGE (256 * GST)
#define G_STAGE  (G_ASTAGE + G_BSTAGE)
#define GEMM_SMEM (3 * G_STAGE * 4)

__global__ __launch_bounds__(256) void gemm_tc(
    const float* __restrict__ A, const float* __restrict__ Bt,
    const float* __restrict__ bias, float* __restrict__ C,
    int Ntot, int roundOut)
{
    extern __shared__ float gsm[];
    const uint32_t smb = smem_u32(gsm);

    const int tid = threadIdx.x;
    const int wid = tid >> 5;
    const int lane = tid & 31;
    const int lg = lane >> 2;
    const int lq = lane & 3;
    const int warp_m = wid & 1;
    const int warp_n = wid >> 1;
    const int mb = warp_m * 64;
    const int nbw = warp_n * 64;
    const int bn = blockIdx.x;
    const int bm = blockIdx.y;

    const float* Ag = A + (size_t)(bm * 128) * GK;
    const float* Bg = Bt + (size_t)(bn * 256) * GK;

    const int a_row = tid >> 2;
    const int a_c4 = (tid & 3) * 4;

    const int a_lm = (mb + (lane & 15)) * GST + ((lane >> 4) & 1) * 4;
    const int b_lm = (nbw + (lane & 7) + ((lane & 16) >> 1)) * GST + ((lane & 8) >> 1);

    float acc[4][8][4];
#pragma unroll
    for (int mt = 0; mt < 4; mt++)
#pragma unroll
        for (int nt = 0; nt < 8; nt++)
#pragma unroll
            for (int i = 0; i < 4; i++) acc[mt][nt][i] = 0.0f;

#define G_ISSUE(kt_, st_) do {                                                  \
        const uint32_t sa_ = smb + ((st_) * G_STAGE) * 4;                       \
        const uint32_t sb_ = sa_ + G_ASTAGE * 4;                                \
        _Pragma("unroll")                                                       \
        for (int i_ = 0; i_ < 2; i_++) {                                        \
            const int row_ = a_row + i_ * 64;                                   \
            CP16(sa_ + (row_ * GST + a_c4) * 4,                                 \
                 Ag + (size_t)row_ * GK + (kt_) * KT + a_c4);                   \
        }                                                                       \
        _Pragma("unroll")                                                       \
        for (int i_ = 0; i_ < 4; i_++) {                                        \
            const int row_ = a_row + i_ * 64;                                   \
            CP16(sb_ + (row_ * GST + a_c4) * 4,                                 \
                 Bg + (size_t)row_ * GK + (kt_) * KT + a_c4);                   \
        }                                                                       \
    } while (0)

    G_ISSUE(0, 0); CP_COMMIT();
    G_ISSUE(1, 1); CP_COMMIT();

    for (int kt = 0; kt < NKT; kt++) {
        CP_WAIT(1);
        __syncthreads();
        if (kt + 2 < NKT) {
            const int st2 = (kt + 2) % 3;
            G_ISSUE(kt + 2, st2);
        }
        CP_COMMIT();

        const int st = kt % 3;
        const uint32_t sa = smb + (st * G_STAGE) * 4;
        const uint32_t sb = sa + G_ASTAGE * 4;

#pragma unroll
        for (int k8 = 0; k8 < 2; k8++) {
            const int k0 = k8 * 8;
            uint32_t af[4][4];
#pragma unroll
            for (int mt = 0; mt < 4; mt++)
                LDMX4(af[mt][0], af[mt][1], af[mt][2], af[mt][3],
                      sa + (a_lm + mt * 16 * GST + k0) * 4);
#pragma unroll
            for (int np = 0; np < 4; np++) {
                uint32_t b0, b1, b2, b3;
                LDMX4(b0, b1, b2, b3, sb + (b_lm + np * 16 * GST + k0) * 4);
#pragma unroll
                for (int mt = 0; mt < 4; mt++) {
                    MMA_TF32(acc[mt][2 * np], af[mt][0], af[mt][1], af[mt][2], af[mt][3], b0, b1);
                    MMA_TF32(acc[mt][2 * np + 1], af[mt][0], af[mt][1], af[mt][2], af[mt][3], b2, b3);
                }
            }
        }
    }
#undef G_ISSUE

#pragma unroll
    for (int mt = 0; mt < 4; mt++) {
        const int row0 = bm * 128 + mb + mt * 16 + lg;
#pragma unroll
        for (int nt = 0; nt < 8; nt++) {
            const int col = bn * 256 + nbw + nt * 8 + 2 * lq;
            const float b0 = bias[col], b1 = bias[col + 1];
            float c0 = acc[mt][nt][0] + b0, c1 = acc[mt][nt][1] + b1;
            float c2 = acc[mt][nt][2] + b0, c3 = acc[mt][nt][3] + b1;
            if (roundOut) {
                c0 = __uint_as_float(cvt_tf32(c0));
                c1 = __uint_as_float(cvt_tf32(c1));
                c2 = __uint_as_float(cvt_tf32(c2));
                c3 = __uint_as_float(cvt_tf32(c3));
            }
            *(float2*)(C + (size_t)row0 * Ntot + col) = make_float2(c0, c1);
            *(float2*)(C + (size_t)(row0 + 8) * Ntot + col) = make_float2(c2, c3);
        }
    }
}

// ---------------------------------------------------------------------------
// Flash attention v3: 128 threads (4 warps), Q tile 64 rows, kv chunks of 64.
// 2 CTAs/SM (smem 87KB) -> one CTA's softmax overlaps the other's mma.
// Scale folded into Q frags; P fed to mma unrounded (HW truncates to tf32).
// Grid: (S/64, H, B), heavy tiles first.
// ---------------------------------------------------------------------------
#define FST 68
#define F_QP (64 * FST)                  // 4352 floats
#define F_KV (64 * FST)                  // 4352 floats
#define F_STAGE (2 * F_KV)               // 8704 floats
#define FLASH_SMEM ((F_QP + 2 * F_STAGE) * 4)   // 87040 B

__global__ __launch_bounds__(128) void flash_mma_kernel(float* __restrict__ y_out)
{
    extern __shared__ float sm[];
    float* Ps = sm;                       // [64][FST], Q staging reused as P
    const uint32_t smb = smem_u32(sm);

    const int tid = threadIdx.x;
    const int wid = tid >> 5;
    const int lane = tid & 31;
    const int lg = lane >> 2;
    const int lq = lane & 3;
    const int mb = wid * 16;

    const int qt = gridDim.x - 1 - blockIdx.x;   // heavy tiles first
    const int h  = blockIdx.y;
    const int b  = blockIdx.z;
    const int q0 = qt * 64;
    const int nchunks = qt + 1;

    const float* qkv = g_qkv;
    const size_t tokbase = (size_t)b * SS * 3 * DD;

    const int f_row = tid >> 4;          // 0..7
    const int f_c4 = (tid & 15) * 4;

    // --- Q tile [64 x 64] via cp.async (pre-rounded tf32 in g_qkv) ---
#pragma unroll
    for (int i = 0; i < 8; i++) {
        const int r = f_row + i * 8;
        CP16(smb + (r * FST + f_c4) * 4,
             qkv + tokbase + (size_t)(q0 + r) * (3 * DD) + h * HD + f_c4);
    }
    CP_COMMIT();

    // --- issue K/V chunk 0 ---
#define F_ISSUE(c_, st_) do {                                                    \
        const uint32_t kb_ = smb + (F_QP + (st_) * F_STAGE) * 4;                 \
        const int k0g_ = (c_) * 64;                                             \
        _Pragma("unroll")                                                        \
        for (int i_ = 0; i_ < 8; i_++) {                                         \
            const int row_ = f_row + i_ * 8;                                     \
            const float* src_ = qkv + tokbase + (size_t)(k0g_ + row_) * (3 * DD) \
                                + DD + h * HD + f_c4;                            \
            const uint32_t dst_ = kb_ + (row_ * FST + f_c4) * 4;                 \
            CP16(dst_, src_);                                                    \
            CP16(dst_ + F_KV * 4, src_ + DD);                                    \
        }                                                                        \
    } while (0)

    F_ISSUE(0, 0); CP_COMMIT();

    // --- hoist Q fragments, fold in softmax scale (0.125 = 2^-3, exact) ---
    CP_WAIT(1);          // Q group done
    __syncthreads();
    uint32_t aq[8][4];
#pragma unroll
    for (int k = 0; k < 8; k++) {
        aq[k][0] = __float_as_uint(0.125f * sm[(mb + lg) * FST + k * 8 + lq]);
        aq[k][1] = __float_as_uint(0.125f * sm[(mb + 8 + lg) * FST + k * 8 + lq]);
        aq[k][2] = __float_as_uint(0.125f * sm[(mb + lg) * FST + k * 8 + lq + 4]);
        aq[k][3] = __float_as_uint(0.125f * sm[(mb + 8 + lg) * FST + k * 8 + lq + 4]);
    }
    __syncthreads();     // Q region free -> Ps

    float o[8][4];
#pragma unroll
    for (int n = 0; n < 8; n++)
#pragma unroll
        for (int i = 0; i < 4; i++) o[n][i] = 0.0f;
    float m0 = -1e30f, m1 = -1e30f, l0 = 0.0f, l1 = 0.0f;

    const int r0g = q0 + mb + lg;
    const int r1g = r0g + 8;

    const int k_lm = ((lane & 7) + ((lane & 16) >> 1)) * FST + ((lane & 8) >> 1);
    const int p_lm = (mb + (lane & 15)) * FST + ((lane >> 4) & 1) * 4;

    for (int c = 0; c < nchunks; c++) {
        const int st = c & 1;
        CP_WAIT(0);
        __syncthreads();
        if (c + 1 < nchunks) F_ISSUE(c + 1, st ^ 1);
        CP_COMMIT();

        const uint32_t ksb = smb + (F_QP + st * F_STAGE) * 4;
        const float* Vs = sm + F_QP + st * F_STAGE + F_KV;
        const int k0g = c * 64;

        // --- S = (Q*scale) @ K^T ---
        float s[8][4];
#pragma unroll
        for (int n = 0; n < 8; n++)
#pragma unroll
            for (int i = 0; i < 4; i++) s[n][i] = 0.0f;

#pragma unroll
        for (int k8 = 0; k8 < 8; k8++) {
#pragma unroll
            for (int np = 0; np < 4; np++) {
                uint32_t b0, b1, b2, b3;
                LDMX4(b0, b1, b2, b3, ksb + (k_lm + np * 16 * FST + k8 * 8) * 4);
                MMA_TF32(s[2 * np], aq[k8][0], aq[k8][1], aq[k8][2], aq[k8][3], b0, b1);
                MMA_TF32(s[2 * np + 1], aq[k8][0], aq[k8][1], aq[k8][2], aq[k8][3], b2, b3);
            }
        }

        // --- causal mask (only the diagonal chunk) ---
        if (c == nchunks - 1) {
#pragma unroll
            for (int n = 0; n < 8; n++) {
                const int col = k0g + n * 8 + 2 * lq;
                if (col     > r0g) s[n][0] = -1e30f;
                if (col + 1 > r0g) s[n][1] = -1e30f;
                if (col     > r1g) s[n][2] = -1e30f;
                if (col + 1 > r1g) s[n][3] = -1e30f;
            }
        }

        // --- online softmax ---
        float mx0 = -1e30f, mx1 = -1e30f;
#pragma unroll
        for (int n = 0; n < 8; n++) {
            mx0 = fmaxf(mx0, fmaxf(s[n][0], s[n][1]));
            mx1 = fmaxf(mx1, fmaxf(s[n][2], s[n][3]));
        }
        mx0 = fmaxf(mx0, __shfl_xor_sync(0xffffffffu, mx0, 1));
        mx0 = fmaxf(mx0, __shfl_xor_sync(0xffffffffu, mx0, 2));
        mx1 = fmaxf(mx1, __shfl_xor_sync(0xffffffffu, mx1, 1));
        mx1 = fmaxf(mx1, __shfl_xor_sync(0xffffffffu, mx1, 2));

        const float mn0 = fmaxf(m0, mx0);
        const float mn1 = fmaxf(m1, mx1);
        const float f0 = exp2f((m0 - mn0) * LOG2E);
        const float f1 = exp2f((m1 - mn1) * LOG2E);

        float sum0 = 0.0f, sum1 = 0.0f;
#pragma unroll
        for (int n = 0; n < 8; n++) {
            float p0 = exp2f((s[n][0] - mn0) * LOG2E);
            float p1 = exp2f((s[n][1] - mn0) * LOG2E);
            float p2 = exp2f((s[n][2] - mn1) * LOG2E);
            float p3 = exp2f((s[n][3] - mn1) * LOG2E);
            sum0 += p0 + p1;
            sum1 += p2 + p3;
            *(float2*)&Ps[(mb + lg) * FST + n * 8 + 2 * lq] = make_float2(p0, p1);
            *(float2*)&Ps[(mb + 8 + lg) * FST + n * 8 + 2 * lq] = make_float2(p2, p3);
        }
        sum0 += __shfl_xor_sync(0xffffffffu, sum0, 1);
        sum0 += __shfl_xor_sync(0xffffffffu, sum0, 2);
        sum1 += __shfl_xor_sync(0xffffffffu, sum1, 1);
        sum1 += __shfl_xor_sync(0xffffffffu, sum1, 2);

        l0 = l0 * f0 + sum0;
        l1 = l1 * f1 + sum1;
        m0 = mn0;
        m1 = mn1;
#pragma unroll
        for (int n = 0; n < 8; n++) {
            o[n][0] *= f0; o[n][1] *= f0;
            o[n][2] *= f1; o[n][3] *= f1;
        }
        __syncwarp();

        // --- O += P @ V ---
#pragma unroll
        for (int k8 = 0; k8 < 8; k8++) {
            uint32_t ap0, ap1, ap2, ap3;
            LDMX4(ap0, ap1, ap2, ap3, smb + (p_lm + k8 * 8) * 4);
#pragma unroll
            for (int n = 0; n < 8; n++) {
                uint32_t b0 = __float_as_uint(Vs[(k8 * 8 + lq) * FST + n * 8 + lg]);
                uint32_t b1 = __float_as_uint(Vs[(k8 * 8 + lq + 4) * FST + n * 8 + lg]);
                MMA_TF32(o[n], ap0, ap1, ap2, ap3, b0, b1);
            }
        }
    }
#undef F_ISSUE

    // --- epilogue: normalize, round to tf32 (feeds proj GEMM), write y ---
    const float inv0 = 1.0f / l0;
    const float inv1 = 1.0f / l1;
#pragma unroll
    for (int n = 0; n < 8; n++) {
        const int col = h * HD + n * 8 + 2 * lq;
        float2 w0 = make_float2(__uint_as_float(cvt_tf32(o[n][0] * inv0)),
                                __uint_as_float(cvt_tf32(o[n][1] * inv0)));
        float2 w1 = make_float2(__uint_as_float(cvt_tf32(o[n][2] * inv1)),
                                __uint_as_float(cvt_tf32(o[n][3] * inv1)));
        *(float2*)(y_out + ((size_t)b * SS + r0g) * DD + col) = w0;
        *(float2*)(y_out + ((size_t)b * SS + r1g) * DD + col) = w1;
    }
}

// ---------------------------------------------------------------------------
// Launch
// ---------------------------------------------------------------------------
extern "C" void kernel_launch(void* const* d_in, const int* in_sizes, int n_in,
                              void* d_out, int out_size)
{
    (void)in_sizes; (void)n_in; (void)out_size;
    const float* x      = (const float*)d_in[0];
    const float* W_attn = (const float*)d_in[1];
    const float* b_attn = (const float*)d_in[2];
    const float* W_proj = (const float*)d_in[3];
    const float* b_proj = (const float*)d_in[4];
    float* out = (float*)d_out;

    float *qkv_p, *y_p, *xc_p, *wta_p, *wtp_p;
    cudaGetSymbolAddress((void**)&qkv_p, g_qkv);
    cudaGetSymbolAddress((void**)&y_p, g_y);
    cudaGetSymbolAddress((void**)&xc_p, g_xc);
    cudaGetSymbolAddress((void**)&wta_p, g_wta);
    cudaGetSymbolAddress((void**)&wtp_p, g_wtp);

    const int M = BB * SS;  // 8192
    cudaFuncSetAttribute(gemm_tc, cudaFuncAttributeMaxDynamicSharedMemorySize, GEMM_SMEM);
    cudaFuncSetAttribute(flash_mma_kernel, cudaFuncAttributeMaxDynamicSharedMemorySize, FLASH_SMEM);

    // 0) Prep: round x; transpose+round weights
    {
        const int n4 = M * DD / 4;
        cvt_round4<<<n4 / 256, 256>>>((const float4*)x, (float4*)xc_p, n4);
        dim3 tb(32, 8);
        transpose_cvt<<<dim3(3 * DD / 32, DD / 32), tb>>>(W_attn, wta_p, DD, 3 * DD);
        transpose_cvt<<<dim3(DD / 32, DD / 32), tb>>>(W_proj, wtp_p, DD, DD);
    }
    // 1) QKV projection (rounds output for flash)
    {
        dim3 grid(3 * DD / 256, M / 128);
        gemm_tc<<<grid, 256, GEMM_SMEM>>>(xc_p, wta_p, b_attn, qkv_p, 3 * DD, 1);
    }
    // 2) Causal flash attention (64-row q tiles, 2 CTAs/SM)
    {
        dim3 grid(SS / 64, HH, BB);
        flash_mma_kernel<<<grid, 128, FLASH_SMEM>>>(y_p);
    }
    // 3) Output projection (fp32 output)
    {
        dim3 grid(DD / 256, M / 128);
        gemm_tc<<<grid, 256, GEMM_SMEM>>>(y_p, wtp_p, b_proj, out, DD, 0);
    }
}